// round 13
// baseline (speedup 1.0000x reference)
#include <cuda_runtime.h>
#include <math.h>

// Problem dims (fixed by the dataset): x (B, K), mu (K, U), out (B, U)
#define B_DIM 8192
#define K_DIM 1024
#define N_DIM 4096
#define KHALF 512     // guard subset: coordinates [0, KHALF)

// GEMM tiling (fallback path; never taken on this dataset)
#define BM 128
#define BN 128
#define BK 16
#define TM 8
#define TN 8
#define APAD 4

#define MTILES (B_DIM / BM)   // 64
#define NTILES (N_DIM / BN)   // 32
#define NT_PER_CTA 8

// Underflow threshold: exp(-t) with t > ~104 rounds to 0 in fp32
#define UNDERFLOW_T 118.0f

// Grid: 1024 xsq CTAs + 256 musq CTAs + 1024 pure-fill CTAs = 2304.
// Every CTA also fills a static contiguous range. Guard = bids [0,256).
#define XSQ_BLOCKS  1024    // 8 rows per CTA (1 per warp), k<512
#define MUSQ_BLOCKS 256     // 16 cols per CTA, k<512
#define NORM_BLOCKS (XSQ_BLOCKS + MUSQ_BLOCKS)   // 1280
#define PURE_BLOCKS 1024
#define WORKERS (NORM_BLOCKS + PURE_BLOCKS)      // 2304
#define GRID_BLOCKS WORKERS
#define GUARD_GROUPS 256

// Static fill shares (float4): 1280*3264 + 1024*4112 = 8388608 = B*N/4  ✓
#define FILL_N 3264
#define FILL_P 4112

// Scratch (no allocations allowed -> device globals).
// PARTIAL norms over k in [0, KHALF) — lower bounds used ONLY by the guard.
__device__ float g_xsq_p[B_DIM];
__device__ float g_musq_p[N_DIM];
__device__ unsigned int g_done = 0;       // norm completion (NORM_BLOCKS)
__device__ unsigned int g_fill_done = 0;  // fill completion (WORKERS)
__device__ unsigned int g_all = 0;        // reset owner

// Contiguous per-CTA fill: sequential address range, streaming stores.
__device__ __forceinline__ void fill_range(float4* __restrict__ o4,
                                           size_t beg, size_t end) {
    const float4 z = make_float4(0.f, 0.f, 0.f, 0.f);
    for (size_t i = beg + threadIdx.x; i < end; i += 256)
        __stcs(&o4[i], z);
}

// ---------------------------------------------------------------------------
// Single fused kernel.
//   bids [0,1024):     xsq slice (8 rows, k<512) -> fill -> guard (bids<256)
//   bids [1024,1280):  musq slice (16 cols, k<512) -> fill
//   bids [1280,2304):  pure fill
// Guard per 128x128 tile: l2 >= (||x_S|| - ||mu_S||)^2, S=[0,512). If
// gamma*bound > 118 every exp underflows to fp32 zero (fill wrote zeros) ->
// skip. Else exact fallback: wait for fill completion (no zero-overwrite
// race), recompute exact tile norms in smem, fp32 GEMM + RBF epilogue —
// correct for ANY input.
// Deadlock-free: fill never waits; spinners (<=256) << resident slots.
// Counters reset by the last CTA overall -> safe under graph replay.
// ---------------------------------------------------------------------------
__global__ __launch_bounds__(256, 6) void fused_rbf_kernel(
    const float* __restrict__ x, const float* __restrict__ mu,
    const float* __restrict__ gamma_p, float* __restrict__ out)
{
    const int tid = threadIdx.x;
    const unsigned bid = blockIdx.x;
    float4* o4 = (float4*)out;

    // ---------------- phase 1: norm slice (norm CTAs only) ----------------
    if (bid < NORM_BLOCKS) {
        if (bid < XSQ_BLOCKS) {
            // xsq: warp w handles row bid*8 + w, k in [0,512)
            const int warp = tid >> 5, lane = tid & 31;
            const int row = bid * 8 + warp;
            const float4* xr = (const float4*)(x + (size_t)row * K_DIM);
            float s = 0.f;
            #pragma unroll
            for (int i = 0; i < 4; i++) {          // 128 float4 = 512 floats
                float4 v = xr[lane + 32 * i];
                s += v.x * v.x + v.y * v.y + v.z * v.z + v.w * v.w;
            }
            #pragma unroll
            for (int o = 16; o > 0; o >>= 1)
                s += __shfl_xor_sync(0xffffffffu, s, o);
            if (lane == 0) g_xsq_p[row] = s;
        } else {
            // musq: CTA covers 16 cols; 16 K-slices of 32 rows each (k<512)
            const int cb = (bid - XSQ_BLOCKS) * 16;
            const int col = cb + (tid & 15);
            const int ks = tid >> 4;               // 0..15
            const float* p = mu + (size_t)(ks * 32) * N_DIM + col;
            float s = 0.f;
            #pragma unroll 8
            for (int i = 0; i < 32; i++) {
                float v = p[(size_t)i * N_DIM];
                s += v * v;
            }
            __shared__ float smn[16][16];
            smn[ks][tid & 15] = s;
            __syncthreads();
            if (tid < 16) {
                float t = 0.f;
                #pragma unroll
                for (int k = 0; k < 16; k++) t += smn[k][tid];
                g_musq_p[cb + tid] = t;
            }
        }
        __threadfence();
        __syncthreads();
        if (tid == 0) atomicAdd(&g_done, 1u);
    }

    // ---------------- phase 2: static fill share (ALL CTAs) ----------------
    {
        size_t beg;
        if (bid < NORM_BLOCKS) beg = (size_t)bid * FILL_N;
        else beg = (size_t)NORM_BLOCKS * FILL_N
                 + (size_t)(bid - NORM_BLOCKS) * FILL_P;
        const size_t end = beg + ((bid < NORM_BLOCKS) ? FILL_N : FILL_P);
        fill_range(o4, beg, end);
    }
    __threadfence();
    __syncthreads();
    if (tid == 0) atomicAdd(&g_fill_done, 1u);

    // ---------------- phase 3: guard + fallback (bids < 256) ----------------
    if (bid < GUARD_GROUPS) {
        const int mt = bid >> 2;                      // 0..63
        const int nt0 = (bid & 3) * NT_PER_CTA;       // 0,8,16,24
        const int block_m = mt * BM;

        if (tid == 0) {
            volatile unsigned int* p = &g_done;
            while (*p < NORM_BLOCKS) __nanosleep(64); // norms done long ago
            __threadfence();
        }
        __syncthreads();

        const float gamma = *gamma_p;

        __shared__ float red_min[8];
        __shared__ float red_max[8];
        {
            const int warp = tid >> 5, lane = tid & 31;
            float v = (tid < 128) ? g_xsq_p[block_m + tid]
                                  : __int_as_float(0x7f800000);
            #pragma unroll
            for (int o = 16; o > 0; o >>= 1)
                v = fminf(v, __shfl_xor_sync(0xffffffffu, v, o));
            if (lane == 0) red_min[warp] = v;

            float mx = 0.f;
            const int base = (nt0 + warp) * BN;
            #pragma unroll
            for (int k = 0; k < 4; k++)
                mx = fmaxf(mx, g_musq_p[base + 32 * k + lane]);
            #pragma unroll
            for (int o = 16; o > 0; o >>= 1)
                mx = fmaxf(mx, __shfl_xor_sync(0xffffffffu, mx, o));
            if (lane == 0) red_max[warp] = mx;
            __syncthreads();
        }
        float rxmin = red_min[0];
        #pragma unroll
        for (int w = 1; w < 8; w++) rxmin = fminf(rxmin, red_min[w]);
        const float rxs = sqrtf(fmaxf(rxmin, 0.f));

        __shared__ float As[BK][BM + APAD];
        __shared__ float Bs[BK][BN];
        __shared__ float xsq_s[BM];
        __shared__ float musq_s[BN];
        __shared__ float part[2][BM];

        bool fill_waited = false;

        for (int j = 0; j < NT_PER_CTA; j++) {
            const float d = rxs - sqrtf(fmaxf(red_max[j], 0.f));
            if (gamma > 0.f && d > 0.f && gamma * d * d > UNDERFLOW_T)
                continue;   // tile provably all-zero; fill wrote zeros

            // ------ fallback: exact tile norms + fp32 GEMM + RBF ------
            if (!fill_waited) {
                if (tid == 0) {
                    volatile unsigned int* p = &g_fill_done;
                    while (*p < WORKERS) __nanosleep(128);
                    __threadfence();
                }
                __syncthreads();
                fill_waited = true;
            }

            const int block_n = (nt0 + j) * BN;

            // exact xsq for the tile's 128 rows
            {
                const int r = tid & 127, h = tid >> 7;
                const float4* xr = (const float4*)(x + (size_t)(block_m + r) * K_DIM)
                                   + h * (K_DIM / 8);
                float s = 0.f;
                for (int i = 0; i < K_DIM / 8; i++) {
                    float4 v = xr[i];
                    s += v.x * v.x + v.y * v.y + v.z * v.z + v.w * v.w;
                }
                __syncthreads();
                part[h][r] = s;
                __syncthreads();
                if (tid < 128) xsq_s[tid] = part[0][tid] + part[1][tid];
            }
            // exact musq for the tile's 128 cols
            {
                const int c = tid & 127, h = tid >> 7;
                const float* p = mu + (size_t)(h * (K_DIM / 2)) * N_DIM + block_n + c;
                float s = 0.f;
                for (int i = 0; i < K_DIM / 2; i++) {
                    float v = p[(size_t)i * N_DIM];
                    s += v * v;
                }
                __syncthreads();
                part[h][c] = s;
                __syncthreads();
                if (tid < 128) musq_s[tid] = part[0][tid] + part[1][tid];
                __syncthreads();
            }

            const int aRow = tid >> 2;
            const int aCol = (tid & 3) * 4;
            const int bRow = tid >> 5;
            const int bCol = (tid & 31) * 4;
            const int ty = tid >> 4;
            const int tx = tid & 15;

            const float* xg = x + (size_t)(block_m + aRow) * K_DIM + aCol;
            const float* bg = mu + (size_t)bRow * N_DIM + block_n + bCol;

            float acc[TM][TN];
            #pragma unroll
            for (int i = 0; i < TM; i++)
                #pragma unroll
                for (int jj = 0; jj < TN; jj++) acc[i][jj] = 0.f;

            for (int k0 = 0; k0 < K_DIM; k0 += BK) {
                float4 a0 = *(const float4*)(xg);
                float4 a1 = *(const float4*)(xg + (size_t)64 * K_DIM);
                As[aCol + 0][aRow] = a0.x;
                As[aCol + 1][aRow] = a0.y;
                As[aCol + 2][aRow] = a0.z;
                As[aCol + 3][aRow] = a0.w;
                As[aCol + 0][aRow + 64] = a1.x;
                As[aCol + 1][aRow + 64] = a1.y;
                As[aCol + 2][aRow + 64] = a1.z;
                As[aCol + 3][aRow + 64] = a1.w;

                float4 b0 = *(const float4*)(bg);
                float4 b1 = *(const float4*)(bg + (size_t)8 * N_DIM);
                *(float4*)&Bs[bRow][bCol]     = b0;
                *(float4*)&Bs[bRow + 8][bCol] = b1;

                __syncthreads();

                #pragma unroll
                for (int k = 0; k < BK; k++) {
                    float a_frag[TM], b_frag[TN];
                    #pragma unroll
                    for (int i = 0; i < TM; i += 4)
                        *(float4*)&a_frag[i] = *(const float4*)&As[k][ty * TM + i];
                    #pragma unroll
                    for (int jj = 0; jj < TN; jj += 4)
                        *(float4*)&b_frag[jj] = *(const float4*)&Bs[k][tx * TN + jj];
                    #pragma unroll
                    for (int i = 0; i < TM; i++)
                        #pragma unroll
                        for (int jj = 0; jj < TN; jj++)
                            acc[i][jj] = fmaf(a_frag[i], b_frag[jj], acc[i][jj]);
                }

                __syncthreads();
                xg += BK;
                bg += (size_t)BK * N_DIM;
            }

            #pragma unroll
            for (int i = 0; i < TM; i++) {
                const int ml = ty * TM + i;
                const int m = block_m + ml;
                const float xs = xsq_s[ml];
                #pragma unroll
                for (int jj = 0; jj < TN; jj += 4) {
                    const int nl = tx * TN + jj;
                    const int n = block_n + nl;
                    float4 r;
                    r.x = expf(-gamma * (xs + musq_s[nl + 0] - 2.f * acc[i][jj + 0]));
                    r.y = expf(-gamma * (xs + musq_s[nl + 1] - 2.f * acc[i][jj + 1]));
                    r.z = expf(-gamma * (xs + musq_s[nl + 2] - 2.f * acc[i][jj + 2]));
                    r.w = expf(-gamma * (xs + musq_s[nl + 3] - 2.f * acc[i][jj + 3]));
                    *(float4*)&out[(size_t)m * N_DIM + n] = r;
                }
            }
            __syncthreads();
        }
    }

    // ---- completion + counter self-reset (last CTA overall resets)
    __syncthreads();
    if (tid == 0) {
        __threadfence();
        if (atomicAdd(&g_all, 1u) == WORKERS - 1) {
            atomicExch(&g_done, 0u);
            atomicExch(&g_fill_done, 0u);
            atomicExch(&g_all, 0u);
        }
    }
}

// ---------------------------------------------------------------------------
// Launch: inputs per metadata order: x (B*K f32), mu (K*U f32), gamma (1 f32)
// ---------------------------------------------------------------------------
extern "C" void kernel_launch(void* const* d_in, const int* in_sizes, int n_in,
                              void* d_out, int out_size) {
    const float* x     = (const float*)d_in[0];
    const float* mu    = (const float*)d_in[1];
    const float* gamma = (const float*)d_in[2];
    float* out = (float*)d_out;

    fused_rbf_kernel<<<GRID_BLOCKS, 256>>>(x, mu, gamma, out);
}

// round 14
// speedup vs baseline: 1.0667x; 1.0667x over previous
#include <cuda_runtime.h>
#include <math.h>

// Problem dims (fixed by the dataset): x (B, K), mu (K, U), out (B, U)
#define B_DIM 8192
#define K_DIM 1024
#define N_DIM 4096
#define KHALF 512     // guard subset: coordinates [0, KHALF)

// GEMM tiling (fallback path; never taken on this dataset)
#define BM 128
#define BN 128
#define BK 16
#define TM 8
#define TN 8
#define APAD 4

#define MTILES (B_DIM / BM)   // 64
#define NTILES (N_DIM / BN)   // 32
#define NT_PER_CTA 8

// Underflow threshold: exp(-t) with t > ~104 rounds to 0 in fp32
#define UNDERFLOW_T 118.0f

// Grid: 256 norm+fill+guard CTAs, 2048 pure-fill CTAs. Static fill split.
// (R12 layout — wave 1 mixes 256 read CTAs with ~600 write CTAs.)
#define XSQ_BLOCKS  128     // 64 rows per CTA
#define MUSQ_BLOCKS 128     // 32 cols per CTA
#define NORM_BLOCKS (XSQ_BLOCKS + MUSQ_BLOCKS)   // 256 (== guard groups)
#define PURE_FILL_BLOCKS 2048
#define WORKERS (NORM_BLOCKS + PURE_FILL_BLOCKS) // 2304
#define GRID_BLOCKS WORKERS

// Static fill shares (float4 each); norm CTAs start late -> smaller share.
// 256*2560 + 2048*3776 = 8388608 = B*N/4  ✓
#define FILL_N 2560
#define FILL_P 3776

// Scratch (no allocations allowed -> device globals).
// PARTIAL norms over k in [0, KHALF) — lower bounds used ONLY by the guard.
__device__ float g_xsq_p[B_DIM];
__device__ float g_musq_p[N_DIM];
__device__ unsigned int g_done = 0;       // norm completion (256)
__device__ unsigned int g_fill_done = 0;  // fill completion (WORKERS)
__device__ unsigned int g_all = 0;        // reset owner

// Contiguous per-CTA fill: each CTA streams a sequential address range.
__device__ __forceinline__ void fill_range(float4* __restrict__ o4,
                                           size_t beg, size_t end) {
    const float4 z = make_float4(0.f, 0.f, 0.f, 0.f);
    for (size_t i = beg + threadIdx.x; i < end; i += 256)
        __stcs(&o4[i], z);
}

// ---------------------------------------------------------------------------
// Single fused kernel (R12 schedule, minBlocks 8 for occupancy).
//   bids [0,128):    partial xsq (k<512) -> fill share -> guard for group bid
//   bids [128,256):  partial musq (k<512) -> fill share -> guard for group bid
//   bids [256,2304): pure fill (static contiguous range)
// Guard per 128x128 tile: l2 >= (||x_S|| - ||mu_S||)^2, S=[0,512). If
// gamma*bound > 118 every exp underflows to fp32 zero (fill wrote zeros) ->
// skip. Else exact fallback: wait for fill completion (no zero-overwrite
// race), recompute exact tile norms in smem, fp32 GEMM + RBF epilogue —
// correct for ANY input.
// Deadlock-free: pure-fill CTAs never wait; spinners (<=256) << slots.
// Counters reset by the last CTA overall -> safe under graph replay.
// ---------------------------------------------------------------------------
__global__ __launch_bounds__(256, 8) void fused_rbf_kernel(
    const float* __restrict__ x, const float* __restrict__ mu,
    const float* __restrict__ gamma_p, float* __restrict__ out)
{
    const int tid = threadIdx.x;
    const unsigned bid = blockIdx.x;
    float4* o4 = (float4*)out;

    if (bid >= NORM_BLOCKS) {
        // ---------------- pure fill CTA ----------------
        const size_t beg = (size_t)NORM_BLOCKS * FILL_N
                         + (size_t)(bid - NORM_BLOCKS) * FILL_P;
        fill_range(o4, beg, beg + FILL_P);
        __threadfence();
        __syncthreads();
        if (tid == 0) {
            atomicAdd(&g_fill_done, 1u);
            __threadfence();
            if (atomicAdd(&g_all, 1u) == WORKERS - 1) {
                atomicExch(&g_done, 0u);
                atomicExch(&g_fill_done, 0u);
                atomicExch(&g_all, 0u);
            }
        }
        return;
    }

    // ================= norm + fill + guard CTA =================
    if (bid < XSQ_BLOCKS) {
        // ---- partial xsq: CTA covers 64 rows; warp w rows w*8..w*8+7
        const int warp = tid >> 5, lane = tid & 31;
        const int row0 = bid * 64 + warp * 8;
        #pragma unroll
        for (int r = 0; r < 8; r++) {
            const float4* xr = (const float4*)(x + (size_t)(row0 + r) * K_DIM);
            float s = 0.f;
            #pragma unroll
            for (int i = 0; i < 4; i++) {          // 128 float4 = 512 floats
                float4 v = xr[lane + 32 * i];
                s += v.x * v.x + v.y * v.y + v.z * v.z + v.w * v.w;
            }
            #pragma unroll
            for (int o = 16; o > 0; o >>= 1)
                s += __shfl_xor_sync(0xffffffffu, s, o);
            if (lane == 0) g_xsq_p[row0 + r] = s;
        }
    } else {
        // ---- partial musq: CTA covers 32 cols; 8 K-slices of 64 rows
        const int cb = (bid - XSQ_BLOCKS) * 32;
        const int col = cb + (tid & 31);
        const int ks = tid >> 5;                   // 0..7
        const float* p = mu + (size_t)(ks * 64) * N_DIM + col;
        float s = 0.f;
        #pragma unroll 8
        for (int i = 0; i < 64; i++) {
            float v = p[(size_t)i * N_DIM];
            s += v * v;
        }
        __shared__ float smn[8][32];
        smn[ks][tid & 31] = s;
        __syncthreads();
        if (tid < 32) {
            float t = 0.f;
            #pragma unroll
            for (int k = 0; k < 8; k++) t += smn[k][tid];
            g_musq_p[cb + tid] = t;
        }
    }
    __threadfence();
    __syncthreads();
    if (tid == 0) atomicAdd(&g_done, 1u);

    // ---- static fill share
    {
        const size_t beg = (size_t)bid * FILL_N;
        fill_range(o4, beg, beg + FILL_N);
    }
    __threadfence();
    __syncthreads();
    if (tid == 0) atomicAdd(&g_fill_done, 1u);

    // ---- guard for tile group bid: mt = bid>>2, nt0 = (bid&3)*8
    const int mt = bid >> 2;
    const int nt0 = (bid & 3) * NT_PER_CTA;
    const int block_m = mt * BM;

    if (tid == 0) {
        volatile unsigned int* p = &g_done;
        while (*p < NORM_BLOCKS) __nanosleep(64);   // norms done long ago
        __threadfence();
    }
    __syncthreads();

    const float gamma = *gamma_p;

    __shared__ float red_min[8];
    __shared__ float red_max[8];
    {
        const int warp = tid >> 5, lane = tid & 31;
        float v = (tid < 128) ? g_xsq_p[block_m + tid] : __int_as_float(0x7f800000);
        #pragma unroll
        for (int o = 16; o > 0; o >>= 1)
            v = fminf(v, __shfl_xor_sync(0xffffffffu, v, o));
        if (lane == 0) red_min[warp] = v;

        float mx = 0.f;
        const int base = (nt0 + warp) * BN;
        #pragma unroll
        for (int k = 0; k < 4; k++)
            mx = fmaxf(mx, g_musq_p[base + 32 * k + lane]);
        #pragma unroll
        for (int o = 16; o > 0; o >>= 1)
            mx = fmaxf(mx, __shfl_xor_sync(0xffffffffu, mx, o));
        if (lane == 0) red_max[warp] = mx;
        __syncthreads();
    }
    float rxmin = red_min[0];
    #pragma unroll
    for (int w = 1; w < 8; w++) rxmin = fminf(rxmin, red_min[w]);
    const float rxs = sqrtf(fmaxf(rxmin, 0.f));

    __shared__ float As[BK][BM + APAD];
    __shared__ float Bs[BK][BN];
    __shared__ float xsq_s[BM];
    __shared__ float musq_s[BN];
    __shared__ float part[2][BM];

    bool fill_waited = false;

    for (int j = 0; j < NT_PER_CTA; j++) {
        const float d = rxs - sqrtf(fmaxf(red_max[j], 0.f));
        if (gamma > 0.f && d > 0.f && gamma * d * d > UNDERFLOW_T)
            continue;   // tile provably all-zero; fill wrote (or writes) zeros

        // -------- fallback: exact tile norms + fp32 GEMM + RBF --------
        if (!fill_waited) {
            if (tid == 0) {
                volatile unsigned int* p = &g_fill_done;
                while (*p < WORKERS) __nanosleep(128);
                __threadfence();
            }
            __syncthreads();
            fill_waited = true;
        }

        const int block_n = (nt0 + j) * BN;

        // exact xsq for the tile's 128 rows
        {
            const int r = tid & 127, h = tid >> 7;
            const float4* xr = (const float4*)(x + (size_t)(block_m + r) * K_DIM)
                               + h * (K_DIM / 8);
            float s = 0.f;
            for (int i = 0; i < K_DIM / 8; i++) {
                float4 v = xr[i];
                s += v.x * v.x + v.y * v.y + v.z * v.z + v.w * v.w;
            }
            __syncthreads();
            part[h][r] = s;
            __syncthreads();
            if (tid < 128) xsq_s[tid] = part[0][tid] + part[1][tid];
        }
        // exact musq for the tile's 128 cols
        {
            const int c = tid & 127, h = tid >> 7;
            const float* p = mu + (size_t)(h * (K_DIM / 2)) * N_DIM + block_n + c;
            float s = 0.f;
            for (int i = 0; i < K_DIM / 2; i++) {
                float v = p[(size_t)i * N_DIM];
                s += v * v;
            }
            __syncthreads();
            part[h][c] = s;
            __syncthreads();
            if (tid < 128) musq_s[tid] = part[0][tid] + part[1][tid];
            __syncthreads();
        }

        const int aRow = tid >> 2;
        const int aCol = (tid & 3) * 4;
        const int bRow = tid >> 5;
        const int bCol = (tid & 31) * 4;
        const int ty = tid >> 4;
        const int tx = tid & 15;

        const float* xg = x + (size_t)(block_m + aRow) * K_DIM + aCol;
        const float* bg = mu + (size_t)bRow * N_DIM + block_n + bCol;

        float acc[TM][TN];
        #pragma unroll
        for (int i = 0; i < TM; i++)
            #pragma unroll
            for (int jj = 0; jj < TN; jj++) acc[i][jj] = 0.f;

        for (int k0 = 0; k0 < K_DIM; k0 += BK) {
            float4 a0 = *(const float4*)(xg);
            float4 a1 = *(const float4*)(xg + (size_t)64 * K_DIM);
            As[aCol + 0][aRow] = a0.x;
            As[aCol + 1][aRow] = a0.y;
            As[aCol + 2][aRow] = a0.z;
            As[aCol + 3][aRow] = a0.w;
            As[aCol + 0][aRow + 64] = a1.x;
            As[aCol + 1][aRow + 64] = a1.y;
            As[aCol + 2][aRow + 64] = a1.z;
            As[aCol + 3][aRow + 64] = a1.w;

            float4 b0 = *(const float4*)(bg);
            float4 b1 = *(const float4*)(bg + (size_t)8 * N_DIM);
            *(float4*)&Bs[bRow][bCol]     = b0;
            *(float4*)&Bs[bRow + 8][bCol] = b1;

            __syncthreads();

            #pragma unroll
            for (int k = 0; k < BK; k++) {
                float a_frag[TM], b_frag[TN];
                #pragma unroll
                for (int i = 0; i < TM; i += 4)
                    *(float4*)&a_frag[i] = *(const float4*)&As[k][ty * TM + i];
                #pragma unroll
                for (int jj = 0; jj < TN; jj += 4)
                    *(float4*)&b_frag[jj] = *(const float4*)&Bs[k][tx * TN + jj];
                #pragma unroll
                for (int i = 0; i < TM; i++)
                    #pragma unroll
                    for (int jj = 0; jj < TN; jj++)
                        acc[i][jj] = fmaf(a_frag[i], b_frag[jj], acc[i][jj]);
            }

            __syncthreads();
            xg += BK;
            bg += (size_t)BK * N_DIM;
        }

        #pragma unroll
        for (int i = 0; i < TM; i++) {
            const int ml = ty * TM + i;
            const int m = block_m + ml;
            const float xs = xsq_s[ml];
            #pragma unroll
            for (int jj = 0; jj < TN; jj += 4) {
                const int nl = tx * TN + jj;
                const int n = block_n + nl;
                float4 r;
                r.x = expf(-gamma * (xs + musq_s[nl + 0] - 2.f * acc[i][jj + 0]));
                r.y = expf(-gamma * (xs + musq_s[nl + 1] - 2.f * acc[i][jj + 1]));
                r.z = expf(-gamma * (xs + musq_s[nl + 2] - 2.f * acc[i][jj + 2]));
                r.w = expf(-gamma * (xs + musq_s[nl + 3] - 2.f * acc[i][jj + 3]));
                *(float4*)&out[(size_t)m * N_DIM + n] = r;
            }
        }
        __syncthreads();
    }

    // ---- completion + counter self-reset (last CTA overall resets)
    __syncthreads();
    if (tid == 0) {
        __threadfence();
        if (atomicAdd(&g_all, 1u) == WORKERS - 1) {
            atomicExch(&g_done, 0u);
            atomicExch(&g_fill_done, 0u);
            atomicExch(&g_all, 0u);
        }
    }
}

// ---------------------------------------------------------------------------
// Launch: inputs per metadata order: x (B*K f32), mu (K*U f32), gamma (1 f32)
// ---------------------------------------------------------------------------
extern "C" void kernel_launch(void* const* d_in, const int* in_sizes, int n_in,
                              void* d_out, int out_size) {
    const float* x     = (const float*)d_in[0];
    const float* mu    = (const float*)d_in[1];
    const float* gamma = (const float*)d_in[2];
    float* out = (float*)d_out;

    fused_rbf_kernel<<<GRID_BLOCKS, 256>>>(x, mu, gamma, out);
}

// round 15
// speedup vs baseline: 1.0922x; 1.0240x over previous
#include <cuda_runtime.h>
#include <math.h>

// Problem dims (fixed by the dataset): x (B, K), mu (K, U), out (B, U)
#define B_DIM 8192
#define K_DIM 1024
#define N_DIM 4096
#define KHALF 512     // guard subset: coordinates [0, KHALF)

// GEMM tiling (fallback path; never taken on this dataset)
#define BM 128
#define BN 128
#define BK 16
#define TM 8
#define TN 8
#define APAD 4

#define MTILES (B_DIM / BM)   // 64
#define NTILES (N_DIM / BN)   // 32
#define NT_PER_CTA 8

// Underflow threshold: exp(-t) with t > ~104 rounds to 0 in fp32
#define UNDERFLOW_T 118.0f

// Grid: 256 norm+guard+fill CTAs, 2048 pure-fill CTAs. Static fill split.
#define XSQ_BLOCKS  128     // 64 rows per CTA
#define MUSQ_BLOCKS 128     // 32 cols per CTA
#define NORM_BLOCKS (XSQ_BLOCKS + MUSQ_BLOCKS)   // 256 (== guard groups)
#define PURE_FILL_BLOCKS 2048
#define WORKERS (NORM_BLOCKS + PURE_FILL_BLOCKS) // 2304
#define GRID_BLOCKS WORKERS

// Static fill shares (float4): norm CTAs do norms+guard first -> smaller.
// 256*2048 + 2048*3840 = 524288 + 7864320 = 8388608 = B*N/4  ✓
#define FILL_N 2048
#define FILL_P 3840

// Scratch (no allocations allowed -> device globals).
// PARTIAL norms over k in [0, KHALF) — lower bounds used ONLY by the guard.
__device__ float g_xsq_p[B_DIM];
__device__ float g_musq_p[N_DIM];
__device__ unsigned int g_done = 0;       // norm completion (256)
__device__ unsigned int g_fill_done = 0;  // fill completion (WORKERS)
__device__ unsigned int g_all = 0;        // reset owner

// Contiguous per-CTA fill: each CTA streams a sequential address range.
__device__ __forceinline__ void fill_range(float4* __restrict__ o4,
                                           size_t beg, size_t end) {
    const float4 z = make_float4(0.f, 0.f, 0.f, 0.f);
    for (size_t i = beg + threadIdx.x; i < end; i += 256)
        __stcs(&o4[i], z);
}

// ---------------------------------------------------------------------------
// Single fused kernel. Phase order per norm CTA:
//   norm slice -> wait(all norms) -> guard reduction (L2-hot, overlapped with
//   pure-fill stores) -> fill share -> [only if some tile failed the guard:
//   wait fill completion, exact fp32 GEMM + RBF fallback].
// Pure-fill CTAs (bids >= 256) just stream zeros over their static range.
// Guard per 128x128 tile: l2 >= (||x_S|| - ||mu_S||)^2, S=[0,512). If
// gamma*bound > 118 every exp underflows to fp32 zero -> the zero fill IS the
// answer. Fallback recomputes exact tile norms in smem -> correct for ANY
// input. Deadlock-free: pure-fill never waits; spinners (<=256) << slots.
// Counters reset by the last CTA overall -> safe under graph replay.
// ---------------------------------------------------------------------------
__global__ __launch_bounds__(256, 6) void fused_rbf_kernel(
    const float* __restrict__ x, const float* __restrict__ mu,
    const float* __restrict__ gamma_p, float* __restrict__ out)
{
    const int tid = threadIdx.x;
    const unsigned bid = blockIdx.x;
    float4* o4 = (float4*)out;

    if (bid >= NORM_BLOCKS) {
        // ---------------- pure fill CTA ----------------
        const size_t beg = (size_t)NORM_BLOCKS * FILL_N
                         + (size_t)(bid - NORM_BLOCKS) * FILL_P;
        fill_range(o4, beg, beg + FILL_P);
        __threadfence();
        __syncthreads();
        if (tid == 0) {
            atomicAdd(&g_fill_done, 1u);
            __threadfence();
            if (atomicAdd(&g_all, 1u) == WORKERS - 1) {
                atomicExch(&g_done, 0u);
                atomicExch(&g_fill_done, 0u);
                atomicExch(&g_all, 0u);
            }
        }
        return;
    }

    // ================= norm + guard + fill CTA =================
    // ---- phase 1: partial norms (k < KHALF)
    if (bid < XSQ_BLOCKS) {
        // CTA covers 64 rows; warp w rows w*8..w*8+7
        const int warp = tid >> 5, lane = tid & 31;
        const int row0 = bid * 64 + warp * 8;
        #pragma unroll
        for (int r = 0; r < 8; r++) {
            const float4* xr = (const float4*)(x + (size_t)(row0 + r) * K_DIM);
            float s = 0.f;
            #pragma unroll
            for (int i = 0; i < 4; i++) {          // 128 float4 = 512 floats
                float4 v = xr[lane + 32 * i];
                s += v.x * v.x + v.y * v.y + v.z * v.z + v.w * v.w;
            }
            #pragma unroll
            for (int o = 16; o > 0; o >>= 1)
                s += __shfl_xor_sync(0xffffffffu, s, o);
            if (lane == 0) g_xsq_p[row0 + r] = s;
        }
    } else {
        // CTA covers 32 cols; 8 K-slices of 64 rows each
        const int cb = (bid - XSQ_BLOCKS) * 32;
        const int col = cb + (tid & 31);
        const int ks = tid >> 5;                   // 0..7
        const float* p = mu + (size_t)(ks * 64) * N_DIM + col;
        float s = 0.f;
        #pragma unroll 8
        for (int i = 0; i < 64; i++) {
            float v = p[(size_t)i * N_DIM];
            s += v * v;
        }
        __shared__ float smn[8][32];
        smn[ks][tid & 31] = s;
        __syncthreads();
        if (tid < 32) {
            float t = 0.f;
            #pragma unroll
            for (int k = 0; k < 8; k++) t += smn[k][tid];
            g_musq_p[cb + tid] = t;
        }
    }
    __threadfence();
    __syncthreads();
    if (tid == 0) atomicAdd(&g_done, 1u);

    // ---- phase 2: wait for all norms (cheap — peers finish ~simultaneously)
    if (tid == 0) {
        volatile unsigned int* p = &g_done;
        while (*p < NORM_BLOCKS) __nanosleep(64);
        __threadfence();
    }
    __syncthreads();

    // ---- phase 3: guard reduction for tile group bid (L2-hot reads)
    const int mt = bid >> 2;                      // 0..63
    const int nt0 = (bid & 3) * NT_PER_CTA;       // 0,8,16,24
    const int block_m = mt * BM;
    const float gamma = *gamma_p;

    __shared__ float red_min[8];
    __shared__ float red_max[8];
    {
        const int warp = tid >> 5, lane = tid & 31;
        float v = (tid < 128) ? g_xsq_p[block_m + tid] : __int_as_float(0x7f800000);
        #pragma unroll
        for (int o = 16; o > 0; o >>= 1)
            v = fminf(v, __shfl_xor_sync(0xffffffffu, v, o));
        if (lane == 0) red_min[warp] = v;

        float mx = 0.f;
        const int base = (nt0 + warp) * BN;
        #pragma unroll
        for (int k = 0; k < 4; k++)
            mx = fmaxf(mx, g_musq_p[base + 32 * k + lane]);
        #pragma unroll
        for (int o = 16; o > 0; o >>= 1)
            mx = fmaxf(mx, __shfl_xor_sync(0xffffffffu, mx, o));
        if (lane == 0) red_max[warp] = mx;
        __syncthreads();
    }
    unsigned need_mask = 0;   // bit j set -> tile nt0+j needs the exact path
    {
        float rxmin = red_min[0];
        #pragma unroll
        for (int w = 1; w < 8; w++) rxmin = fminf(rxmin, red_min[w]);
        const float rxs = sqrtf(fmaxf(rxmin, 0.f));
        #pragma unroll
        for (int j = 0; j < NT_PER_CTA; j++) {
            const float d = rxs - sqrtf(fmaxf(red_max[j], 0.f));
            if (!(gamma > 0.f && d > 0.f && gamma * d * d > UNDERFLOW_T))
                need_mask |= (1u << j);
        }
    }

    // ---- phase 4: fill share (the common-case final work of this CTA)
    {
        const size_t beg = (size_t)bid * FILL_N;
        fill_range(o4, beg, beg + FILL_N);
    }
    __threadfence();
    __syncthreads();
    if (tid == 0) atomicAdd(&g_fill_done, 1u);

    // ---- phase 5: exact fallback for tiles that failed the guard (rare)
    if (need_mask != 0) {
        // wait for ALL fill to land so GEMM results aren't overwritten
        if (tid == 0) {
            volatile unsigned int* p = &g_fill_done;
            while (*p < WORKERS) __nanosleep(128);
            __threadfence();
        }
        __syncthreads();

        __shared__ float As[BK][BM + APAD];
        __shared__ float Bs[BK][BN];
        __shared__ float xsq_s[BM];
        __shared__ float musq_s[BN];
        __shared__ float part[2][BM];

        for (int j = 0; j < NT_PER_CTA; j++) {
            if (!(need_mask & (1u << j))) continue;
            const int block_n = (nt0 + j) * BN;

            // exact xsq for the tile's 128 rows
            {
                const int r = tid & 127, h = tid >> 7;
                const float4* xr = (const float4*)(x + (size_t)(block_m + r) * K_DIM)
                                   + h * (K_DIM / 8);
                float s = 0.f;
                for (int i = 0; i < K_DIM / 8; i++) {
                    float4 v = xr[i];
                    s += v.x * v.x + v.y * v.y + v.z * v.z + v.w * v.w;
                }
                __syncthreads();
                part[h][r] = s;
                __syncthreads();
                if (tid < 128) xsq_s[tid] = part[0][tid] + part[1][tid];
            }
            // exact musq for the tile's 128 cols
            {
                const int c = tid & 127, h = tid >> 7;
                const float* p = mu + (size_t)(h * (K_DIM / 2)) * N_DIM + block_n + c;
                float s = 0.f;
                for (int i = 0; i < K_DIM / 2; i++) {
                    float v = p[(size_t)i * N_DIM];
                    s += v * v;
                }
                __syncthreads();
                part[h][c] = s;
                __syncthreads();
                if (tid < 128) musq_s[tid] = part[0][tid] + part[1][tid];
                __syncthreads();
            }

            const int aRow = tid >> 2;
            const int aCol = (tid & 3) * 4;
            const int bRow = tid >> 5;
            const int bCol = (tid & 31) * 4;
            const int ty = tid >> 4;
            const int tx = tid & 15;

            const float* xg = x + (size_t)(block_m + aRow) * K_DIM + aCol;
            const float* bg = mu + (size_t)bRow * N_DIM + block_n + bCol;

            float acc[TM][TN];
            #pragma unroll
            for (int i = 0; i < TM; i++)
                #pragma unroll
                for (int jj = 0; jj < TN; jj++) acc[i][jj] = 0.f;

            for (int k0 = 0; k0 < K_DIM; k0 += BK) {
                float4 a0 = *(const float4*)(xg);
                float4 a1 = *(const float4*)(xg + (size_t)64 * K_DIM);
                As[aCol + 0][aRow] = a0.x;
                As[aCol + 1][aRow] = a0.y;
                As[aCol + 2][aRow] = a0.z;
                As[aCol + 3][aRow] = a0.w;
                As[aCol + 0][aRow + 64] = a1.x;
                As[aCol + 1][aRow + 64] = a1.y;
                As[aCol + 2][aRow + 64] = a1.z;
                As[aCol + 3][aRow + 64] = a1.w;

                float4 b0 = *(const float4*)(bg);
                float4 b1 = *(const float4*)(bg + (size_t)8 * N_DIM);
                *(float4*)&Bs[bRow][bCol]     = b0;
                *(float4*)&Bs[bRow + 8][bCol] = b1;

                __syncthreads();

                #pragma unroll
                for (int k = 0; k < BK; k++) {
                    float a_frag[TM], b_frag[TN];
                    #pragma unroll
                    for (int i = 0; i < TM; i += 4)
                        *(float4*)&a_frag[i] = *(const float4*)&As[k][ty * TM + i];
                    #pragma unroll
                    for (int jj = 0; jj < TN; jj += 4)
                        *(float4*)&b_frag[jj] = *(const float4*)&Bs[k][tx * TN + jj];
                    #pragma unroll
                    for (int i = 0; i < TM; i++)
                        #pragma unroll
                        for (int jj = 0; jj < TN; jj++)
                            acc[i][jj] = fmaf(a_frag[i], b_frag[jj], acc[i][jj]);
                }

                __syncthreads();
                xg += BK;
                bg += (size_t)BK * N_DIM;
            }

            #pragma unroll
            for (int i = 0; i < TM; i++) {
                const int ml = ty * TM + i;
                const int m = block_m + ml;
                const float xs = xsq_s[ml];
                #pragma unroll
                for (int jj = 0; jj < TN; jj += 4) {
                    const int nl = tx * TN + jj;
                    const int n = block_n + nl;
                    float4 r;
                    r.x = expf(-gamma * (xs + musq_s[nl + 0] - 2.f * acc[i][jj + 0]));
                    r.y = expf(-gamma * (xs + musq_s[nl + 1] - 2.f * acc[i][jj + 1]));
                    r.z = expf(-gamma * (xs + musq_s[nl + 2] - 2.f * acc[i][jj + 2]));
                    r.w = expf(-gamma * (xs + musq_s[nl + 3] - 2.f * acc[i][jj + 3]));
                    *(float4*)&out[(size_t)m * N_DIM + n] = r;
                }
            }
            __syncthreads();
        }
    }

    // ---- completion + counter self-reset (last CTA overall resets)
    __syncthreads();
    if (tid == 0) {
        __threadfence();
        if (atomicAdd(&g_all, 1u) == WORKERS - 1) {
            atomicExch(&g_done, 0u);
            atomicExch(&g_fill_done, 0u);
            atomicExch(&g_all, 0u);
        }
    }
}

// ---------------------------------------------------------------------------
// Launch: inputs per metadata order: x (B*K f32), mu (K*U f32), gamma (1 f32)
// ---------------------------------------------------------------------------
extern "C" void kernel_launch(void* const* d_in, const int* in_sizes, int n_in,
                              void* d_out, int out_size) {
    const float* x     = (const float*)d_in[0];
    const float* mu    = (const float*)d_in[1];
    const float* gamma = (const float*)d_in[2];
    float* out = (float*)d_out;

    fused_rbf_kernel<<<GRID_BLOCKS, 256>>>(x, mu, gamma, out);
}

// round 16
// speedup vs baseline: 1.0935x; 1.0012x over previous
#include <cuda_runtime.h>
#include <math.h>

// Problem dims (fixed by the dataset): x (B, K), mu (K, U), out (B, U)
#define B_DIM 8192
#define K_DIM 1024
#define N_DIM 4096
#define KHALF 512     // guard subset: coordinates [0, KHALF)

// GEMM tiling (fallback path; never taken on this dataset)
#define BM 128
#define BN 128
#define BK 16
#define TM 8
#define TN 8
#define APAD 4

#define MTILES (B_DIM / BM)   // 64
#define NTILES (N_DIM / BN)   // 32
#define NT_PER_CTA 8

// Underflow threshold: exp(-t) with t > ~104 rounds to 0 in fp32
#define UNDERFLOW_T 118.0f

// Grid: 256 norm+guard+fill CTAs, 2048 pure-fill CTAs. Static fill split.
#define XSQ_BLOCKS  128     // 64 rows per CTA
#define MUSQ_BLOCKS 128     // 32 cols per CTA
#define NORM_BLOCKS (XSQ_BLOCKS + MUSQ_BLOCKS)   // 256 (== guard groups)
#define PURE_FILL_BLOCKS 2048
#define WORKERS (NORM_BLOCKS + PURE_FILL_BLOCKS) // 2304
#define GRID_BLOCKS WORKERS

// Static fill shares (float4): norm CTAs do norms+guard first -> smaller.
// 256*2048 + 2048*3840 = 8388608 = B*N/4  ✓
#define FILL_N 2048
#define FILL_P 3840

// Scratch (no allocations allowed -> device globals).
// PARTIAL norms over k in [0, KHALF) — lower bounds used ONLY by the guard.
__device__ float g_xsq_p[B_DIM];
__device__ float g_musq_p[N_DIM];
__device__ unsigned int g_done = 0;       // norm completion (256)
__device__ unsigned int g_fill_done = 0;  // fill completion (WORKERS)
__device__ unsigned int g_all = 0;        // reset owner

// Contiguous per-CTA fill: each CTA streams a sequential address range.
__device__ __forceinline__ void fill_range(float4* __restrict__ o4,
                                           size_t beg, size_t end) {
    const float4 z = make_float4(0.f, 0.f, 0.f, 0.f);
    for (size_t i = beg + threadIdx.x; i < end; i += 256)
        __stcs(&o4[i], z);
}

// ---------------------------------------------------------------------------
// Single fused kernel (R15 schedule, MLP-improved norm phase).
//   norm CTAs: norm slice -> wait(all norms) -> guard reduction -> fill share
//              -> [fallback GEMM only for tiles failing the guard].
//   pure-fill CTAs: stream zeros over a static contiguous range.
// Guard per 128x128 tile: l2 >= (||x_S|| - ||mu_S||)^2, S=[0,512). If
// gamma*bound > 118 every exp underflows to fp32 zero -> zero fill IS the
// answer. Fallback recomputes exact tile norms in smem -> correct for ANY
// input. Deadlock-free: pure-fill never waits; spinners (<=256) << slots.
// Counters reset by the last CTA overall -> safe under graph replay.
// ---------------------------------------------------------------------------
__global__ __launch_bounds__(256, 6) void fused_rbf_kernel(
    const float* __restrict__ x, const float* __restrict__ mu,
    const float* __restrict__ gamma_p, float* __restrict__ out)
{
    const int tid = threadIdx.x;
    const unsigned bid = blockIdx.x;
    float4* o4 = (float4*)out;

    if (bid >= NORM_BLOCKS) {
        // ---------------- pure fill CTA ----------------
        const size_t beg = (size_t)NORM_BLOCKS * FILL_N
                         + (size_t)(bid - NORM_BLOCKS) * FILL_P;
        fill_range(o4, beg, beg + FILL_P);
        __threadfence();
        __syncthreads();
        if (tid == 0) {
            atomicAdd(&g_fill_done, 1u);
            __threadfence();
            if (atomicAdd(&g_all, 1u) == WORKERS - 1) {
                atomicExch(&g_done, 0u);
                atomicExch(&g_fill_done, 0u);
                atomicExch(&g_all, 0u);
            }
        }
        return;
    }

    // ================= norm + guard + fill CTA =================
    // ---- phase 1: partial norms (k < KHALF), high-MLP layout
    if (bid < XSQ_BLOCKS) {
        // CTA covers 64 rows; warp w rows w*8..w*8+7.
        // Chunk-outer / row-inner: 8 independent loads per iteration (MLP>=8).
        const int warp = tid >> 5, lane = tid & 31;
        const int row0 = bid * 64 + warp * 8;
        float s[8];
        #pragma unroll
        for (int r = 0; r < 8; r++) s[r] = 0.f;
        #pragma unroll
        for (int i = 0; i < 4; i++) {              // 4 chunks x 8 rows
            #pragma unroll
            for (int r = 0; r < 8; r++) {
                float4 v = ((const float4*)(x + (size_t)(row0 + r) * K_DIM))
                               [lane + 32 * i];
                s[r] += v.x * v.x + v.y * v.y + v.z * v.z + v.w * v.w;
            }
        }
        #pragma unroll
        for (int r = 0; r < 8; r++) {
            float t = s[r];
            #pragma unroll
            for (int o = 16; o > 0; o >>= 1)
                t += __shfl_xor_sync(0xffffffffu, t, o);
            if (lane == 0) g_xsq_p[row0 + r] = t;
        }
    } else {
        // CTA covers 32 cols; 8 K-slices of 64 rows each, unroll 16 (MLP 16)
        const int cb = (bid - XSQ_BLOCKS) * 32;
        const int col = cb + (tid & 31);
        const int ks = tid >> 5;                   // 0..7
        const float* p = mu + (size_t)(ks * 64) * N_DIM + col;
        float s = 0.f;
        #pragma unroll 16
        for (int i = 0; i < 64; i++) {
            float v = p[(size_t)i * N_DIM];
            s += v * v;
        }
        __shared__ float smn[8][32];
        smn[ks][tid & 31] = s;
        __syncthreads();
        if (tid < 32) {
            float t = 0.f;
            #pragma unroll
            for (int k = 0; k < 8; k++) t += smn[k][tid];
            g_musq_p[cb + tid] = t;
        }
    }
    __threadfence();
    __syncthreads();
    if (tid == 0) atomicAdd(&g_done, 1u);

    // ---- phase 2: wait for all norms (cheap — peers finish ~simultaneously)
    if (tid == 0) {
        volatile unsigned int* p = &g_done;
        while (*p < NORM_BLOCKS) __nanosleep(64);
        __threadfence();
    }
    __syncthreads();

    // ---- phase 3: guard reduction for tile group bid (L2-hot reads)
    const int mt = bid >> 2;                      // 0..63
    const int nt0 = (bid & 3) * NT_PER_CTA;       // 0,8,16,24
    const int block_m = mt * BM;
    const float gamma = *gamma_p;

    __shared__ float red_min[8];
    __shared__ float red_max[8];
    {
        const int warp = tid >> 5, lane = tid & 31;
        float v = (tid < 128) ? g_xsq_p[block_m + tid] : __int_as_float(0x7f800000);
        #pragma unroll
        for (int o = 16; o > 0; o >>= 1)
            v = fminf(v, __shfl_xor_sync(0xffffffffu, v, o));
        if (lane == 0) red_min[warp] = v;

        float mx = 0.f;
        const int base = (nt0 + warp) * BN;
        #pragma unroll
        for (int k = 0; k < 4; k++)
            mx = fmaxf(mx, g_musq_p[base + 32 * k + lane]);
        #pragma unroll
        for (int o = 16; o > 0; o >>= 1)
            mx = fmaxf(mx, __shfl_xor_sync(0xffffffffu, mx, o));
        if (lane == 0) red_max[warp] = mx;
        __syncthreads();
    }
    unsigned need_mask = 0;   // bit j set -> tile nt0+j needs the exact path
    {
        float rxmin = red_min[0];
        #pragma unroll
        for (int w = 1; w < 8; w++) rxmin = fminf(rxmin, red_min[w]);
        const float rxs = sqrtf(fmaxf(rxmin, 0.f));
        #pragma unroll
        for (int j = 0; j < NT_PER_CTA; j++) {
            const float d = rxs - sqrtf(fmaxf(red_max[j], 0.f));
            if (!(gamma > 0.f && d > 0.f && gamma * d * d > UNDERFLOW_T))
                need_mask |= (1u << j);
        }
    }

    // ---- phase 4: fill share (the common-case final work of this CTA)
    {
        const size_t beg = (size_t)bid * FILL_N;
        fill_range(o4, beg, beg + FILL_N);
    }
    __threadfence();
    __syncthreads();
    if (tid == 0) atomicAdd(&g_fill_done, 1u);

    // ---- phase 5: exact fallback for tiles that failed the guard (rare)
    if (need_mask != 0) {
        if (tid == 0) {
            volatile unsigned int* p = &g_fill_done;
            while (*p < WORKERS) __nanosleep(128);
            __threadfence();
        }
        __syncthreads();

        __shared__ float As[BK][BM + APAD];
        __shared__ float Bs[BK][BN];
        __shared__ float xsq_s[BM];
        __shared__ float musq_s[BN];
        __shared__ float part[2][BM];

        for (int j = 0; j < NT_PER_CTA; j++) {
            if (!(need_mask & (1u << j))) continue;
            const int block_n = (nt0 + j) * BN;

            // exact xsq for the tile's 128 rows
            {
                const int r = tid & 127, h = tid >> 7;
                const float4* xr = (const float4*)(x + (size_t)(block_m + r) * K_DIM)
                                   + h * (K_DIM / 8);
                float s = 0.f;
                for (int i = 0; i < K_DIM / 8; i++) {
                    float4 v = xr[i];
                    s += v.x * v.x + v.y * v.y + v.z * v.z + v.w * v.w;
                }
                __syncthreads();
                part[h][r] = s;
                __syncthreads();
                if (tid < 128) xsq_s[tid] = part[0][tid] + part[1][tid];
            }
            // exact musq for the tile's 128 cols
            {
                const int c = tid & 127, h = tid >> 7;
                const float* p = mu + (size_t)(h * (K_DIM / 2)) * N_DIM + block_n + c;
                float s = 0.f;
                for (int i = 0; i < K_DIM / 2; i++) {
                    float v = p[(size_t)i * N_DIM];
                    s += v * v;
                }
                __syncthreads();
                part[h][c] = s;
                __syncthreads();
                if (tid < 128) musq_s[tid] = part[0][tid] + part[1][tid];
                __syncthreads();
            }

            const int aRow = tid >> 2;
            const int aCol = (tid & 3) * 4;
            const int bRow = tid >> 5;
            const int bCol = (tid & 31) * 4;
            const int ty = tid >> 4;
            const int tx = tid & 15;

            const float* xg = x + (size_t)(block_m + aRow) * K_DIM + aCol;
            const float* bg = mu + (size_t)bRow * N_DIM + block_n + bCol;

            float acc[TM][TN];
            #pragma unroll
            for (int i = 0; i < TM; i++)
                #pragma unroll
                for (int jj = 0; jj < TN; jj++) acc[i][jj] = 0.f;

            for (int k0 = 0; k0 < K_DIM; k0 += BK) {
                float4 a0 = *(const float4*)(xg);
                float4 a1 = *(const float4*)(xg + (size_t)64 * K_DIM);
                As[aCol + 0][aRow] = a0.x;
                As[aCol + 1][aRow] = a0.y;
                As[aCol + 2][aRow] = a0.z;
                As[aCol + 3][aRow] = a0.w;
                As[aCol + 0][aRow + 64] = a1.x;
                As[aCol + 1][aRow + 64] = a1.y;
                As[aCol + 2][aRow + 64] = a1.z;
                As[aCol + 3][aRow + 64] = a1.w;

                float4 b0 = *(const float4*)(bg);
                float4 b1 = *(const float4*)(bg + (size_t)8 * N_DIM);
                *(float4*)&Bs[bRow][bCol]     = b0;
                *(float4*)&Bs[bRow + 8][bCol] = b1;

                __syncthreads();

                #pragma unroll
                for (int k = 0; k < BK; k++) {
                    float a_frag[TM], b_frag[TN];
                    #pragma unroll
                    for (int i = 0; i < TM; i += 4)
                        *(float4*)&a_frag[i] = *(const float4*)&As[k][ty * TM + i];
                    #pragma unroll
                    for (int jj = 0; jj < TN; jj += 4)
                        *(float4*)&b_frag[jj] = *(const float4*)&Bs[k][tx * TN + jj];
                    #pragma unroll
                    for (int i = 0; i < TM; i++)
                        #pragma unroll
                        for (int jj = 0; jj < TN; jj++)
                            acc[i][jj] = fmaf(a_frag[i], b_frag[jj], acc[i][jj]);
                }

                __syncthreads();
                xg += BK;
                bg += (size_t)BK * N_DIM;
            }

            #pragma unroll
            for (int i = 0; i < TM; i++) {
                const int ml = ty * TM + i;
                const int m = block_m + ml;
                const float xs = xsq_s[ml];
                #pragma unroll
                for (int jj = 0; jj < TN; jj += 4) {
                    const int nl = tx * TN + jj;
                    const int n = block_n + nl;
                    float4 r;
                    r.x = expf(-gamma * (xs + musq_s[nl + 0] - 2.f * acc[i][jj + 0]));
                    r.y = expf(-gamma * (xs + musq_s[nl + 1] - 2.f * acc[i][jj + 1]));
                    r.z = expf(-gamma * (xs + musq_s[nl + 2] - 2.f * acc[i][jj + 2]));
                    r.w = expf(-gamma * (xs + musq_s[nl + 3] - 2.f * acc[i][jj + 3]));
                    *(float4*)&out[(size_t)m * N_DIM + n] = r;
                }
            }
            __syncthreads();
        }
    }

    // ---- completion + counter self-reset (last CTA overall resets)
    __syncthreads();
    if (tid == 0) {
        __threadfence();
        if (atomicAdd(&g_all, 1u) == WORKERS - 1) {
            atomicExch(&g_done, 0u);
            atomicExch(&g_fill_done, 0u);
            atomicExch(&g_all, 0u);
        }
    }
}

// ---------------------------------------------------------------------------
// Launch: inputs per metadata order: x (B*K f32), mu (K*U f32), gamma (1 f32)
// ---------------------------------------------------------------------------
extern "C" void kernel_launch(void* const* d_in, const int* in_sizes, int n_in,
                              void* d_out, int out_size) {
    const float* x     = (const float*)d_in[0];
    const float* mu    = (const float*)d_in[1];
    const float* gamma = (const float*)d_in[2];
    float* out = (float*)d_out;

    fused_rbf_kernel<<<GRID_BLOCKS, 256>>>(x, mu, gamma, out);
}